// round 2
// baseline (speedup 1.0000x reference)
#include <cuda_runtime.h>
#include <cuda_fp16.h>

#define NN 100000
#define EE 3200000
#define MM 1066666
#define GG 1024
#define HID 32

// ---------------- scratch (device globals; allocation-free) ----------------
__device__ float    d_splut[4];        // {1, sp0, sp1, sp2} decode LUT
__device__ float    d_Wc[14 * 32];     // folded input->hidden weight
__device__ float    d_bc[32];          // folded bias
__device__ unsigned d_ewp[EE];         // packed edge-weight priority (0..3)
__device__ float    d_deg[NN];         // degree, then rsqrt(deg)
__device__ __half   d_hw2[NN * HID];   // x @ Wc + bc, fp16
__device__ float    d_acc[NN * HID];   // aggregation accumulator (f32)
__device__ float    d_g[GG * HID];     // pooled graph features

__device__ __forceinline__ float gelu_exact(float x) {
    return 0.5f * x * (1.0f + erff(x * 0.70710678118654752f));
}

__device__ __forceinline__ void red_add_f32(float* p, float v) {
    asm volatile("red.global.add.f32 [%0], %1;" :: "l"(p), "f"(v) : "memory");
}

__device__ __forceinline__ void red_add_v4(float* p, float4 v) {
    asm volatile("red.global.add.v4.f32 [%0], {%1,%2,%3,%4};"
                 :: "l"(p), "f"(v.x), "f"(v.y), "f"(v.z), "f"(v.w) : "memory");
}

// ---------------- k1: softmax + LUT + weight folding -----------------------
__global__ void k_prep(const float* __restrict__ msg_w,
                       const float* __restrict__ emb_W,
                       const float* __restrict__ emb_b,
                       const float* __restrict__ gcn_W) {
    int j = threadIdx.x;
    if (j == 0) {
        float m = fmaxf(msg_w[0], fmaxf(msg_w[1], msg_w[2]));
        float e0 = expf(msg_w[0] - m);
        float e1 = expf(msg_w[1] - m);
        float e2 = expf(msg_w[2] - m);
        float inv = 1.0f / (e0 + e1 + e2);
        d_splut[0] = 1.0f;
        d_splut[1] = e0 * inv; d_splut[2] = e1 * inv; d_splut[3] = e2 * inv;
    }
    if (j < 32) {
        float a0 = 0.f, a1 = 0.f, ab = 0.f;
        #pragma unroll
        for (int k = 0; k < 52; k++) {
            float gw = gcn_W[k * 32 + j];
            a0 += emb_W[k] * gw;
            a1 += emb_W[52 + k] * gw;
            ab += emb_b[k] * gw;
        }
        d_Wc[0 * 32 + j] = a0;
        d_Wc[1 * 32 + j] = a1;
        d_bc[j] = ab;
        #pragma unroll
        for (int f = 0; f < 12; f++)
            d_Wc[(2 + f) * 32 + j] = gcn_W[(52 + f) * 32 + j];
    }
}

// ---------------- k2: fills (ewp=0, deg=1 self-loop, g=0) ------------------
__global__ void k_fill() {
    int i = blockIdx.x * blockDim.x + threadIdx.x;
    uint4 z4u = make_uint4(0u, 0u, 0u, 0u);
    if (i < EE / 4) reinterpret_cast<uint4*>(d_ewp)[i] = z4u;
    if (i < NN)     d_deg[i] = 1.0f;
    if (i < (GG * HID) / 4)
        reinterpret_cast<float4*>(d_g)[i] = make_float4(0.f, 0.f, 0.f, 0.f);
}

// ---------------- k3: merged priority scatter (max == last-write order) ----
__global__ void k_scatter_all(const int* __restrict__ known,
                              const int* __restrict__ unk,
                              const int* __restrict__ obs) {
    int i = blockIdx.x * blockDim.x + threadIdx.x;
    if (i >= 3 * MM) return;
    int idx; unsigned prio;
    if (i < MM)            { idx = known[i];          prio = 1u; }
    else if (i < 2 * MM)   { idx = unk[i - MM];       prio = 2u; }
    else                   { idx = obs[i - 2 * MM];   prio = 3u; }
    atomicMax(&d_ewp[idx], prio);
}

// ---------------- k4: degree accumulation ----------------------------------
__global__ void k_deg(const int* __restrict__ ei) {
    int e = blockIdx.x * blockDim.x + threadIdx.x;
    if (e >= EE) return;
    float4 lut = *reinterpret_cast<const float4*>(d_splut);
    const float* lp = &lut.x;
    float ew = lp[d_ewp[e]];
    red_add_f32(&d_deg[ei[EE + e]], ew);
}

// ---------------- k5: per-node hw (fp16), dis, self-loop init --------------
__global__ void k_node(const float* __restrict__ x) {
    __shared__ float sW[14 * 32];
    __shared__ float sb[32];
    int tid = threadIdx.x;
    for (int i = tid; i < 14 * 32; i += blockDim.x) sW[i] = d_Wc[i];
    if (tid < 32) sb[tid] = d_bc[tid];
    __syncthreads();

    int n = blockIdx.x * blockDim.x + tid;
    if (n >= NN) return;

    float xv[14];
    #pragma unroll
    for (int k = 0; k < 14; k++) xv[k] = x[n * 14 + k];

    float dis = rsqrtf(d_deg[n]);
    d_deg[n] = dis;
    float dis2 = dis * dis;

    __half2* hwp = reinterpret_cast<__half2*>(d_hw2) + n * 16;
    float4*  accp = reinterpret_cast<float4*>(d_acc) + n * 8;

    #pragma unroll
    for (int q = 0; q < 8; q++) {
        float4 o;
        float* op = &o.x;
        #pragma unroll
        for (int s = 0; s < 4; s++) {
            int j = q * 4 + s;
            float acc = sb[j];
            #pragma unroll
            for (int k = 0; k < 14; k++) acc += xv[k] * sW[k * 32 + j];
            op[s] = acc;
        }
        hwp[q * 2 + 0] = __floats2half2_rn(o.x, o.y);
        hwp[q * 2 + 1] = __floats2half2_rn(o.z, o.w);
        o.x *= dis2; o.y *= dis2; o.z *= dis2; o.w *= dis2;
        accp[q] = o;
    }
}

// ---------------- k6: edge aggregation (4 lanes/edge, fp16 gather) ---------
__global__ void k_edge(const int* __restrict__ ei) {
    unsigned t = blockIdx.x * blockDim.x + threadIdx.x;  // EE*4 threads exact
    unsigned lane = threadIdx.x & 31;
    unsigned e0 = (t >> 5) * 8;           // 8 edges per warp
    unsigned sl = lane & 7;
    unsigned grp = lane >> 3;
    unsigned me = e0 + sl;

    // phase 1: parallel metadata loads across lane groups
    int rv = 0, cv = 0;
    float ewv = 0.f;
    if (grp == 0) rv = ei[me];
    else if (grp == 1) cv = ei[EE + me];
    else if (grp == 2) {
        float4 lut = *reinterpret_cast<const float4*>(d_splut);
        const float* lp = &lut.x;
        ewv = lp[d_ewp[me]];
    }
    float dis = 0.f;
    if (grp == 0) dis = d_deg[rv];
    else if (grp == 1) dis = d_deg[cv];

    // phase 2: combine weight on lanes 0-7
    float disc = __shfl_sync(0xFFFFFFFFu, dis, sl + 8);
    float eww  = __shfl_sync(0xFFFFFFFFu, ewv, sl + 16);
    float wcomb = dis * disc * eww;       // valid on lanes 0-7

    // phase 3: broadcast per-edge values (edge el = lane>>2, sub = lane&3)
    unsigned el  = lane >> 2;
    unsigned sub = lane & 3;
    int   r = __shfl_sync(0xFFFFFFFFu, rv, el);
    int   c = __shfl_sync(0xFFFFFFFFu, cv, el + 8);
    float w = __shfl_sync(0xFFFFFFFFu, wcomb, el);

    // phase 4: gather 16B fp16 (8 values), scale, RED 32B f32
    uint4 hv = reinterpret_cast<const uint4*>(d_hw2)[r * 4 + sub];
    __half2* h = reinterpret_cast<__half2*>(&hv);
    float2 f0 = __half22float2(h[0]);
    float2 f1 = __half22float2(h[1]);
    float2 f2 = __half22float2(h[2]);
    float2 f3 = __half22float2(h[3]);
    float* base = d_acc + c * 32 + sub * 8;
    red_add_v4(base,     make_float4(f0.x * w, f0.y * w, f1.x * w, f1.y * w));
    red_add_v4(base + 4, make_float4(f2.x * w, f2.y * w, f3.x * w, f3.y * w));
}

// ---------------- k7: gelu + global_add_pool -------------------------------
__global__ void k_pool(const int* __restrict__ batch,
                       const float* __restrict__ gcn_b) {
    unsigned t = blockIdx.x * blockDim.x + threadIdx.x;  // NN*8 threads exact
    unsigned n = t >> 3;
    unsigned lane = t & 7;
    int b = 0;
    if (lane == 0) b = batch[n];
    b = __shfl_sync(0xFFFFFFFFu, b, 0, 8);

    float4 v  = reinterpret_cast<const float4*>(d_acc)[n * 8 + lane];
    float4 bb = reinterpret_cast<const float4*>(gcn_b)[lane];
    v.x = gelu_exact(v.x + bb.x);
    v.y = gelu_exact(v.y + bb.y);
    v.z = gelu_exact(v.z + bb.z);
    v.w = gelu_exact(v.w + bb.w);
    red_add_v4(d_g + b * 32 + lane * 4, v);
}

// ---------------- k8: backbone MLP -----------------------------------------
__global__ void k_mlp(const float* __restrict__ fc1_W,
                      const float* __restrict__ fc1_b,
                      const float* __restrict__ fc2_W,
                      const float* __restrict__ fc2_b,
                      float* __restrict__ out) {
    __shared__ float sW1[32 * 32];
    __shared__ float sb1[32];
    __shared__ float sW2[32];
    int tid = threadIdx.x;
    for (int i = tid; i < 1024; i += blockDim.x) sW1[i] = fc1_W[i];
    if (tid < 32) { sb1[tid] = fc1_b[tid]; sW2[tid] = fc2_W[tid]; }
    __syncthreads();

    int g = blockIdx.x * blockDim.x + tid;
    if (g >= GG) return;

    float gv[32];
    #pragma unroll
    for (int k = 0; k < 32; k++) gv[k] = d_g[g * 32 + k];

    float acc = fc2_b[0];
    #pragma unroll
    for (int j = 0; j < 32; j++) {
        float s = sb1[j];
        #pragma unroll
        for (int k = 0; k < 32; k++) s += gv[k] * sW1[k * 32 + j];
        acc += gelu_exact(s) * sW2[j];
    }
    out[g] = acc;
}

// ---------------- launch ----------------------------------------------------
extern "C" void kernel_launch(void* const* d_in, const int* in_sizes, int n_in,
                              void* d_out, int out_size) {
    const float* x     = (const float*)d_in[0];
    const int*   ei    = (const int*)  d_in[1];
    const int*   batch = (const int*)  d_in[2];
    const int*   known = (const int*)  d_in[3];
    const int*   unk   = (const int*)  d_in[4];
    const int*   obs   = (const int*)  d_in[5];
    const float* msg_w = (const float*)d_in[6];
    const float* emb_W = (const float*)d_in[7];
    const float* emb_b = (const float*)d_in[8];
    const float* gcn_W = (const float*)d_in[9];
    const float* gcn_b = (const float*)d_in[10];
    const float* fc1_W = (const float*)d_in[11];
    const float* fc1_b = (const float*)d_in[12];
    const float* fc2_W = (const float*)d_in[13];
    const float* fc2_b = (const float*)d_in[14];
    float* out = (float*)d_out;

    k_prep<<<1, 32>>>(msg_w, emb_W, emb_b, gcn_W);
    k_fill<<<(EE / 4 + 255) / 256, 256>>>();
    k_scatter_all<<<(3 * MM + 255) / 256, 256>>>(known, unk, obs);
    k_deg<<<(EE + 255) / 256, 256>>>(ei);
    k_node<<<(NN + 255) / 256, 256>>>(x);
    k_edge<<<(EE * 4) / 256, 256>>>(ei);           // launch #6 -> ncu capture
    k_pool<<<(NN * 8) / 256, 256>>>(batch, gcn_b);
    k_mlp<<<(GG + 255) / 256, 256>>>(fc1_W, fc1_b, fc2_W, fc2_b, out);
}

// round 5
// speedup vs baseline: 1.0722x; 1.0722x over previous
#include <cuda_runtime.h>
#include <cuda_fp16.h>

#define NN 100000
#define EE 3200000
#define MM 1066666
#define GG 1024
#define HID 32

// ---------------- scratch (device globals; allocation-free) ----------------
__device__ float    d_splut[4];        // {1, sp0, sp1, sp2} decode LUT
__device__ float    d_Wc[14 * 32];     // folded input->hidden weight
__device__ float    d_bc[32];          // folded bias
__device__ unsigned d_ewp[EE];         // edge-weight priority (0..3)
__device__ float    d_deg[NN];         // degree, then rsqrt(deg)
__device__ __half   d_hws[NN * HID];   // dis[n] * (x @ Wc + bc), fp16
__device__ float    d_acc[NN * HID];   // aggregation accumulator (f32)
__device__ float    d_g[GG * HID];     // pooled graph features

__device__ __forceinline__ float gelu_exact(float x) {
    return 0.5f * x * (1.0f + erff(x * 0.70710678118654752f));
}

__device__ __forceinline__ void red_add_f32(float* p, float v) {
    asm volatile("red.global.add.f32 [%0], %1;" :: "l"(p), "f"(v) : "memory");
}

__device__ __forceinline__ void red_add_v4(float* p, float4 v) {
    asm volatile("red.global.add.v4.f32 [%0], {%1,%2,%3,%4};"
                 :: "l"(p), "f"(v.x), "f"(v.y), "f"(v.z), "f"(v.w) : "memory");
}

// ---------------- k1: softmax + LUT + weight folding -----------------------
__global__ void k_prep(const float* __restrict__ msg_w,
                       const float* __restrict__ emb_W,
                       const float* __restrict__ emb_b,
                       const float* __restrict__ gcn_W) {
    int j = threadIdx.x;
    if (j == 0) {
        float m = fmaxf(msg_w[0], fmaxf(msg_w[1], msg_w[2]));
        float e0 = expf(msg_w[0] - m);
        float e1 = expf(msg_w[1] - m);
        float e2 = expf(msg_w[2] - m);
        float inv = 1.0f / (e0 + e1 + e2);
        d_splut[0] = 1.0f;
        d_splut[1] = e0 * inv; d_splut[2] = e1 * inv; d_splut[3] = e2 * inv;
    }
    if (j < 32) {
        float a0 = 0.f, a1 = 0.f, ab = 0.f;
        #pragma unroll
        for (int k = 0; k < 52; k++) {
            float gw = gcn_W[k * 32 + j];
            a0 += emb_W[k] * gw;
            a1 += emb_W[52 + k] * gw;
            ab += emb_b[k] * gw;
        }
        d_Wc[0 * 32 + j] = a0;
        d_Wc[1 * 32 + j] = a1;
        d_bc[j] = ab;
        #pragma unroll
        for (int f = 0; f < 12; f++)
            d_Wc[(2 + f) * 32 + j] = gcn_W[(52 + f) * 32 + j];
    }
}

// ---------------- k2: fills (ewp=0, deg=1 self-loop, g=0) ------------------
__global__ void k_fill() {
    int i = blockIdx.x * blockDim.x + threadIdx.x;
    if (i < EE / 4) reinterpret_cast<uint4*>(d_ewp)[i] = make_uint4(0u, 0u, 0u, 0u);
    if (i < NN)     d_deg[i] = 1.0f;
    if (i < (GG * HID) / 4)
        reinterpret_cast<float4*>(d_g)[i] = make_float4(0.f, 0.f, 0.f, 0.f);
}

// ---------------- k3: merged priority scatter (max == last-write order) ----
// 4 indices per thread, vectorized metadata load.
__global__ void k_scatter_all(const int* __restrict__ known,
                              const int* __restrict__ unk,
                              const int* __restrict__ obs) {
    const int nq = (MM + 3) / 4;                   // quads per mask
    int i = blockIdx.x * blockDim.x + threadIdx.x;
    if (i >= 3 * nq) return;
    const int* src; unsigned prio; int q;
    if (i < nq)            { src = known; prio = 1u; q = i; }
    else if (i < 2 * nq)   { src = unk;   prio = 2u; q = i - nq; }
    else                   { src = obs;   prio = 3u; q = i - 2 * nq; }
    int base = q * 4;
    if (base + 3 < MM) {
        int4 v = *reinterpret_cast<const int4*>(src + base);
        atomicMax(&d_ewp[v.x], prio);
        atomicMax(&d_ewp[v.y], prio);
        atomicMax(&d_ewp[v.z], prio);
        atomicMax(&d_ewp[v.w], prio);
    } else {
        for (int k = base; k < MM; k++) atomicMax(&d_ewp[src[k]], prio);
    }
}

// ---------------- k4: degree accumulation (4 edges/thread) -----------------
__global__ void k_deg(const int* __restrict__ ei) {
    __shared__ float slut[4];
    if (threadIdx.x < 4) slut[threadIdx.x] = d_splut[threadIdx.x];
    __syncthreads();
    int i = blockIdx.x * blockDim.x + threadIdx.x;   // EE/4 threads exact
    if (i >= EE / 4) return;
    int4  c4 = reinterpret_cast<const int4*>(ei + EE)[i];
    uint4 p4 = reinterpret_cast<const uint4*>(d_ewp)[i];
    red_add_f32(&d_deg[c4.x], slut[p4.x & 3]);
    red_add_f32(&d_deg[c4.y], slut[p4.y & 3]);
    red_add_f32(&d_deg[c4.z], slut[p4.z & 3]);
    red_add_f32(&d_deg[c4.w], slut[p4.w & 3]);
}

// ---------------- k5: per-node hws (fp16), dis, acc init -------------------
__global__ void k_node(const float* __restrict__ x) {
    __shared__ float sW[14 * 32];
    __shared__ float sb[32];
    int tid = threadIdx.x;
    for (int i = tid; i < 14 * 32; i += blockDim.x) sW[i] = d_Wc[i];
    if (tid < 32) sb[tid] = d_bc[tid];
    __syncthreads();

    int n = blockIdx.x * blockDim.x + tid;
    if (n >= NN) return;

    float xv[14];
    #pragma unroll
    for (int k = 0; k < 14; k++) xv[k] = x[n * 14 + k];

    float dis = rsqrtf(d_deg[n]);
    d_deg[n] = dis;                               // store rsqrt(deg)

    __half2* hwp  = reinterpret_cast<__half2*>(d_hws) + n * 16;
    float4*  accp = reinterpret_cast<float4*>(d_acc)  + n * 8;

    #pragma unroll
    for (int q = 0; q < 8; q++) {
        float4 o;
        float* op = &o.x;
        #pragma unroll
        for (int s = 0; s < 4; s++) {
            int j = q * 4 + s;
            float acc = sb[j];
            #pragma unroll
            for (int k = 0; k < 14; k++) acc += xv[k] * sW[k * 32 + j];
            op[s] = acc * dis;                    // hws = dis * hw
        }
        hwp[q * 2 + 0] = __floats2half2_rn(o.x, o.y);
        hwp[q * 2 + 1] = __floats2half2_rn(o.z, o.w);
        accp[q] = o;                              // self-loop term (× dis[c] later)
    }
}

// ---------------- k6: edge aggregation (4 lanes/edge, fp16 gather) ---------
// acc[c] += ew[e] * hws[r]; no degree gathers (folded into hws and k_pool).
__global__ void k_edge(const int* __restrict__ ei) {
    __shared__ float slut[4];
    if (threadIdx.x < 4) slut[threadIdx.x] = d_splut[threadIdx.x];
    __syncthreads();

    unsigned t = blockIdx.x * blockDim.x + threadIdx.x;  // EE*4 threads exact
    unsigned lane = threadIdx.x & 31;
    unsigned e0 = (t >> 5) * 8;                   // 8 edges per warp
    unsigned sl = lane & 7;
    unsigned grp = lane >> 3;

    // coalesced metadata loads, one 8-edge span per lane group
    int v = 0; float ewv = 0.f;
    if (grp == 0)       v = ei[e0 + sl];              // r
    else if (grp == 1)  v = ei[EE + e0 + sl];         // c
    else if (grp == 2)  ewv = slut[d_ewp[e0 + sl] & 3];

    unsigned el  = lane >> 2;                     // edge index within warp
    unsigned sub = lane & 3;                      // quarter-row index
    int   r = __shfl_sync(0xFFFFFFFFu, v, el);
    int   c = __shfl_sync(0xFFFFFFFFu, v, el + 8);
    float w = __shfl_sync(0xFFFFFFFFu, ewv, el + 16);

    // gather 16B fp16 (8 values), scale, RED 32B f32
    uint4 hv = reinterpret_cast<const uint4*>(d_hws)[r * 4 + sub];
    __half2* h = reinterpret_cast<__half2*>(&hv);
    float2 f0 = __half22float2(h[0]);
    float2 f1 = __half22float2(h[1]);
    float2 f2 = __half22float2(h[2]);
    float2 f3 = __half22float2(h[3]);
    float* base = d_acc + c * 32 + sub * 8;
    red_add_v4(base,     make_float4(f0.x * w, f0.y * w, f1.x * w, f1.y * w));
    red_add_v4(base + 4, make_float4(f2.x * w, f2.y * w, f3.x * w, f3.y * w));
}

// ---------------- k7: dis[c] scale + bias + gelu + global_add_pool ---------
__global__ void k_pool(const int* __restrict__ batch,
                       const float* __restrict__ gcn_b) {
    unsigned t = blockIdx.x * blockDim.x + threadIdx.x;  // NN*8 threads exact
    unsigned n = t >> 3;
    unsigned lane = t & 7;
    int   b   = batch[n];                         // 8-lane broadcast load
    float dis = d_deg[n];                         // rsqrt(deg), broadcast

    float4 v  = reinterpret_cast<const float4*>(d_acc)[n * 8 + lane];
    float4 bb = reinterpret_cast<const float4*>(gcn_b)[lane];
    v.x = gelu_exact(v.x * dis + bb.x);
    v.y = gelu_exact(v.y * dis + bb.y);
    v.z = gelu_exact(v.z * dis + bb.z);
    v.w = gelu_exact(v.w * dis + bb.w);
    red_add_v4(d_g + b * 32 + lane * 4, v);
}

// ---------------- k8: backbone MLP -----------------------------------------
__global__ void k_mlp(const float* __restrict__ fc1_W,
                      const float* __restrict__ fc1_b,
                      const float* __restrict__ fc2_W,
                      const float* __restrict__ fc2_b,
                      float* __restrict__ out) {
    __shared__ float sW1[32 * 32];
    __shared__ float sb1[32];
    __shared__ float sW2[32];
    int tid = threadIdx.x;
    for (int i = tid; i < 1024; i += blockDim.x) sW1[i] = fc1_W[i];
    if (tid < 32) { sb1[tid] = fc1_b[tid]; sW2[tid] = fc2_W[tid]; }
    __syncthreads();

    int g = blockIdx.x * blockDim.x + tid;
    if (g >= GG) return;

    float gv[32];
    #pragma unroll
    for (int k = 0; k < 32; k++) gv[k] = d_g[g * 32 + k];

    float acc = fc2_b[0];
    #pragma unroll
    for (int j = 0; j < 32; j++) {
        float s = sb1[j];
        #pragma unroll
        for (int k = 0; k < 32; k++) s += gv[k] * sW1[k * 32 + j];
        acc += gelu_exact(s) * sW2[j];
    }
    out[g] = acc;
}

// ---------------- launch ----------------------------------------------------
extern "C" void kernel_launch(void* const* d_in, const int* in_sizes, int n_in,
                              void* d_out, int out_size) {
    const float* x     = (const float*)d_in[0];
    const int*   ei    = (const int*)  d_in[1];
    const int*   batch = (const int*)  d_in[2];
    const int*   known = (const int*)  d_in[3];
    const int*   unk   = (const int*)  d_in[4];
    const int*   obs   = (const int*)  d_in[5];
    const float* msg_w = (const float*)d_in[6];
    const float* emb_W = (const float*)d_in[7];
    const float* emb_b = (const float*)d_in[8];
    const float* gcn_W = (const float*)d_in[9];
    const float* gcn_b = (const float*)d_in[10];
    const float* fc1_W = (const float*)d_in[11];
    const float* fc1_b = (const float*)d_in[12];
    const float* fc2_W = (const float*)d_in[13];
    const float* fc2_b = (const float*)d_in[14];
    float* out = (float*)d_out;

    const int nq = (MM + 3) / 4;

    k_prep<<<1, 32>>>(msg_w, emb_W, emb_b, gcn_W);
    k_fill<<<(EE / 4 + 255) / 256, 256>>>();
    k_scatter_all<<<(3 * nq + 255) / 256, 256>>>(known, unk, obs);
    k_deg<<<(EE / 4 + 255) / 256, 256>>>(ei);
    k_node<<<(NN + 255) / 256, 256>>>(x);
    k_edge<<<(EE * 4) / 256, 256>>>(ei);           // launch #6 -> ncu capture
    k_pool<<<(NN * 8) / 256, 256>>>(batch, gcn_b);
    k_mlp<<<(GG + 255) / 256, 256>>>(fc1_W, fc1_b, fc2_W, fc2_b, out);
}